// round 2
// baseline (speedup 1.0000x reference)
#include <cuda_runtime.h>
#include <cstdint>

// QuantizationLayer: q = rint(x*8 - 0.5) (round-half-to-even), q in [0,7],
// out bits MSB-first: out[3*i + j] = (q_i >> (2-j)) & 1, as float.
//
// Pure streaming kernel: 128 MiB in, 384 MiB out, no reuse -> HBM-bound.
// Vectorized: each thread reads one float4 (4 elems = 16B) and writes
// 3 float4 (12 floats = 48B, contiguous, 16B-aligned).

__global__ __launch_bounds__(256) void quant_bits_kernel(
    const float4* __restrict__ in, float4* __restrict__ out, int n_vec)
{
    int idx = blockIdx.x * blockDim.x + threadIdx.x;
    if (idx >= n_vec) return;

    float4 v = in[idx];

    // round-half-to-even via cvt.rni (matches jnp.round / tf.round)
    int q0 = __float2int_rn(fmaf(v.x, 8.0f, -0.5f));
    int q1 = __float2int_rn(fmaf(v.y, 8.0f, -0.5f));
    int q2 = __float2int_rn(fmaf(v.z, 8.0f, -0.5f));
    int q3 = __float2int_rn(fmaf(v.w, 8.0f, -0.5f));

    // 12 output floats: for each elem, bits (q>>2)&1, (q>>1)&1, q&1 (MSB first)
    float4 o0 = make_float4((float)((q0 >> 2) & 1),
                            (float)((q0 >> 1) & 1),
                            (float)( q0       & 1),
                            (float)((q1 >> 2) & 1));
    float4 o1 = make_float4((float)((q1 >> 1) & 1),
                            (float)( q1       & 1),
                            (float)((q2 >> 2) & 1),
                            (float)((q2 >> 1) & 1));
    float4 o2 = make_float4((float)( q2       & 1),
                            (float)((q3 >> 2) & 1),
                            (float)((q3 >> 1) & 1),
                            (float)( q3       & 1));

    // Output offset: idx * 12 floats = idx * 48 bytes -> 16B aligned
    float4* o = out + (size_t)idx * 3;
    o[0] = o0;
    o[1] = o1;
    o[2] = o2;
}

// Scalar tail for n not divisible by 4 (never launched for this shape).
__global__ void quant_bits_tail_kernel(
    const float* __restrict__ in, float* __restrict__ out, int start, int n)
{
    int i = start + blockIdx.x * blockDim.x + threadIdx.x;
    if (i >= n) return;
    int q = __float2int_rn(fmaf(in[i], 8.0f, -0.5f));
    out[3 * i + 0] = (float)((q >> 2) & 1);
    out[3 * i + 1] = (float)((q >> 1) & 1);
    out[3 * i + 2] = (float)( q       & 1);
}

extern "C" void kernel_launch(void* const* d_in, const int* in_sizes, int n_in,
                              void* d_out, int out_size)
{
    const float* x = (const float*)d_in[0];
    float* out = (float*)d_out;
    int n = in_sizes[0];          // 65536 * 512 = 33,554,432
    int n_vec = n / 4;            // 8,388,608 float4 loads

    if (n_vec > 0) {
        int threads = 256;
        int blocks = (n_vec + threads - 1) / threads;
        quant_bits_kernel<<<blocks, threads>>>(
            (const float4*)x, (float4*)out, n_vec);
    }
    int tail_start = n_vec * 4;
    if (tail_start < n) {
        int tail = n - tail_start;
        quant_bits_tail_kernel<<<(tail + 127) / 128, 128>>>(x, out, tail_start, n);
    }
}